// round 16
// baseline (speedup 1.0000x reference)
#include <cuda_runtime.h>

#define NMO_   40
#define ROWS_  16
#define CSTR   12     // floats per stored MO column (48B, 16B-aligned, good bank spread)
#define CPB    64     // configs per block (128 thr = 64 cfg x 2 spins)
#define TPB    128
#define PIV_TAU 1e-4f

__device__ __forceinline__ float frcp_fast(float x) {
    float r;
    asm("rcp.approx.f32 %0, %1;" : "=f"(r) : "f"(x));
    return r;
}

// One thread per 8x8 Slater determinant — UNPIVOTED STREAMING LU, no shuffles.
// Phase 1: factor the left 4-column panel (static unrolled; 32 floats live),
//          keep only the 22 L-multipliers.
// Phase 2: stream columns 4..7 one at a time: load, forward-apply L (and the
//          accumulated step-4..6 multipliers), capture the pivot, discard.
// Peak live state ~48 floats. Launch bound 10 caps regs at 51 (vs 64 at
// bound 8) -> 1280 thr/SM instead of 1024: the R15 profile showed a pure
// latency-bound kernel (no pipe >40%, issue 38%, occ 33%), so occupancy is
// the binding resource, and 51 regs still clears the ~48-float live state.
// Tiny-pivot guard: rare per-thread redo in fp64 with partial pivoting on a
// dynamically-indexed LOCAL array (costs the hot path zero registers).
__global__ __launch_bounds__(TPB, 10)
void slater_det_kernel(const float* __restrict__ mo,
                       const int*   __restrict__ cup,
                       const int*   __restrict__ cdown,
                       float*       __restrict__ out,
                       int nconf)
{
    __shared__ __align__(16) float mo_sh[2 * NMO_ * CSTR];  // 960 floats
    __shared__ float sh_det[2 * CPB];

    const int b  = blockIdx.y;
    const int c0 = blockIdx.x * CPB;
    const int t  = threadIdx.x;

    // Stage column-major: mo_sh[(s*40+col)*12 + row8] = mo[b, s*8+row8, col]
    {
        const float* src = mo + (size_t)b * (ROWS_ * NMO_);
        #pragma unroll
        for (int idx = t; idx < ROWS_ * NMO_; idx += TPB) {
            const int e   = idx / NMO_;
            const int col = idx % NMO_;
            mo_sh[((e >> 3) * NMO_ + col) * CSTR + (e & 7)] = src[idx];
        }
    }
    __syncthreads();

    const int s  = t >> 6;                // spin channel
    const int cl = t & (CPB - 1);         // local config
    const int c  = c0 + cl;

    const int*   cw   = ((s == 0) ? cup : cdown) + c * 8;
    const float* base = mo_sh + s * NMO_ * CSTR;

    float detA = 1.0f, detB = 1.0f;
    float minp = 1e30f;

    // ---- Phase 1: gather + factor columns 0..3 (P[j][i] = elem(row i, col j)) ----
    float P[4][8];
    {
        const int4 ci = __ldg((const int4*)cw);
        const int c4[4] = {ci.x, ci.y, ci.z, ci.w};
        #pragma unroll
        for (int j = 0; j < 4; ++j) {
            const float4 lo = *reinterpret_cast<const float4*>(base + c4[j] * CSTR);
            const float4 hi = *reinterpret_cast<const float4*>(base + c4[j] * CSTR + 4);
            P[j][0] = lo.x; P[j][1] = lo.y; P[j][2] = lo.z; P[j][3] = lo.w;
            P[j][4] = hi.x; P[j][5] = hi.y; P[j][6] = hi.z; P[j][7] = hi.w;
        }
    }
    #pragma unroll
    for (int k = 0; k < 4; ++k) {
        const float piv = P[k][k];
        minp = fminf(minp, fabsf(piv));
        if (k & 1) detB *= piv; else detA *= piv;
        const float inv = frcp_fast(piv);
        #pragma unroll
        for (int i = k + 1; i < 8; ++i) P[k][i] *= inv;        // L[i][k]
        #pragma unroll
        for (int j = k + 1; j < 4; ++j)
            #pragma unroll
            for (int i = k + 1; i < 8; ++i)
                P[j][i] = fmaf(-P[k][i], P[j][k], P[j][i]);
    }
    // Live from phase 1: only the L entries P[k][i], i > k.

    // ---- Phase 2: stream columns 4..7 ----
    float m45 = 0.f, m46 = 0.f, m47 = 0.f,    // step-4 multipliers
          m56 = 0.f, m57 = 0.f,               // step-5
          m67 = 0.f;                          // step-6
    const int4 ci2 = __ldg((const int4*)cw + 1);
    const int c8[4] = {ci2.x, ci2.y, ci2.z, ci2.w};

    #pragma unroll
    for (int j = 4; j < 8; ++j) {
        float cv[8];
        {
            const float4 lo = *reinterpret_cast<const float4*>(base + c8[j - 4] * CSTR);
            const float4 hi = *reinterpret_cast<const float4*>(base + c8[j - 4] * CSTR + 4);
            cv[0] = lo.x; cv[1] = lo.y; cv[2] = lo.z; cv[3] = lo.w;
            cv[4] = hi.x; cv[5] = hi.y; cv[6] = hi.z; cv[7] = hi.w;
        }
        // forward-apply panel-1 eliminations
        #pragma unroll
        for (int k = 0; k < 4; ++k)
            #pragma unroll
            for (int i = k + 1; i < 8; ++i)
                cv[i] = fmaf(-P[k][i], cv[k], cv[i]);
        // forward-apply step 4..j-1 multipliers
        if (j > 4) { cv[5] = fmaf(-m45, cv[4], cv[5]);
                     cv[6] = fmaf(-m46, cv[4], cv[6]);
                     cv[7] = fmaf(-m47, cv[4], cv[7]); }
        if (j > 5) { cv[6] = fmaf(-m56, cv[5], cv[6]);
                     cv[7] = fmaf(-m57, cv[5], cv[7]); }
        if (j > 6) { cv[7] = fmaf(-m67, cv[6], cv[7]); }

        const float piv = cv[j];
        minp = fminf(minp, fabsf(piv));
        if (j & 1) detB *= piv; else detA *= piv;

        if (j < 7) {
            const float inv = frcp_fast(piv);
            if (j == 4) { m45 = cv[5] * inv; m46 = cv[6] * inv; m47 = cv[7] * inv; }
            if (j == 5) { m56 = cv[6] * inv; m57 = cv[7] * inv; }
            if (j == 6) { m67 = cv[7] * inv; }
        }
    }

    float det = detA * detB;

    // ---- rare path: fp64 pivoted LU on a local array (dynamic indexing ->
    //      local memory; zero register cost to the hot path) ----
    if (minp < PIV_TAU) {
        double m[64];
        #pragma unroll 1
        for (int j = 0; j < 8; ++j) {
            const int col = cw[j];
            #pragma unroll 1
            for (int i = 0; i < 8; ++i)
                m[i * 8 + j] = (double)base[col * CSTR + i];
        }
        double dd = 1.0;
        #pragma unroll 1
        for (int k = 0; k < 8; ++k) {
            int p = k;
            double mx = fabs(m[k * 8 + k]);
            for (int i = k + 1; i < 8; ++i) {
                const double v = fabs(m[i * 8 + k]);
                if (v > mx) { mx = v; p = i; }
            }
            if (p != k) {
                dd = -dd;
                for (int j2 = k; j2 < 8; ++j2) {
                    const double tmp = m[k * 8 + j2];
                    m[k * 8 + j2] = m[p * 8 + j2];
                    m[p * 8 + j2] = tmp;
                }
            }
            const double piv = m[k * 8 + k];
            dd *= piv;
            const double iv = 1.0 / piv;
            for (int i = k + 1; i < 8; ++i) {
                const double f = m[i * 8 + k] * iv;
                for (int j2 = k + 1; j2 < 8; ++j2)
                    m[i * 8 + j2] -= f * m[k * 8 + j2];
            }
        }
        det = (float)dd;
    }

    sh_det[t] = det;
    __syncthreads();

    // Combine spins; coalesced 256B store per block.
    if (t < CPB)
        out[(size_t)b * nconf + c0 + t] = sh_det[t] * sh_det[CPB + t];
}

extern "C" void kernel_launch(void* const* d_in, const int* in_sizes, int n_in,
                              void* d_out, int out_size)
{
    const float* mo    = (const float*)d_in[0];  // (B, 16, 40) f32
    const int*   cup   = (const int*)  d_in[1];  // (C, 8) i32
    const int*   cdown = (const int*)  d_in[2];  // (C, 8) i32
    float*       out   = (float*)d_out;          // (B, C) f32

    const int B = in_sizes[0] / (ROWS_ * NMO_);
    const int C = in_sizes[1] / 8;

    dim3 grid(C / CPB, B);
    slater_det_kernel<<<grid, TPB>>>(mo, cup, cdown, out, C);
}

// round 17
// speedup vs baseline: 1.1316x; 1.1316x over previous
#include <cuda_runtime.h>

#define NMO_   40
#define ROWS_  16
#define CSTR   12     // floats per stored MO column (48B, 16B-aligned, good bank spread)
#define CPB    64     // configs per block (128 thr = 64 cfg x 2 spins)
#define TPB    128
#define PIV_TAU 1e-4f

__device__ __forceinline__ float frcp_fast(float x) {
    float r;
    asm("rcp.approx.f32 %0, %1;" : "=f"(r) : "f"(x));
    return r;
}

// One thread per 8x8 Slater determinant — UNPIVOTED LU via panel + Schur.
// Phase 1: factor the left 4-column panel (static unrolled), keep 22 L-mults.
// Phase 2: load ALL FOUR trailing columns and forward-apply the panel stage
//          by stage ACROSS columns — the four chains are independent (4-way
//          ILP), collapsing the critical path that made the streaming version
//          (R15/R16) latency-bound. Rows 0..3 die as stages retire.
// Phase 3: 4x4 Schur complement LU (4 short steps).
// Tiny-pivot guard: rare per-thread redo in fp64 with partial pivoting on a
// local array (zero register cost to the hot path).
__global__ __launch_bounds__(TPB, 8)
void slater_det_kernel(const float* __restrict__ mo,
                       const int*   __restrict__ cup,
                       const int*   __restrict__ cdown,
                       float*       __restrict__ out,
                       int nconf)
{
    __shared__ __align__(16) float mo_sh[2 * NMO_ * CSTR];  // 960 floats
    __shared__ float sh_det[2 * CPB];

    const int b  = blockIdx.y;
    const int c0 = blockIdx.x * CPB;
    const int t  = threadIdx.x;

    // Stage column-major: mo_sh[(s*40+col)*12 + row8] = mo[b, s*8+row8, col]
    {
        const float* src = mo + (size_t)b * (ROWS_ * NMO_);
        #pragma unroll
        for (int idx = t; idx < ROWS_ * NMO_; idx += TPB) {
            const int e   = idx / NMO_;
            const int col = idx % NMO_;
            mo_sh[((e >> 3) * NMO_ + col) * CSTR + (e & 7)] = src[idx];
        }
    }
    __syncthreads();

    const int s  = t >> 6;                // spin channel
    const int cl = t & (CPB - 1);         // local config
    const int c  = c0 + cl;

    const int*   cw   = ((s == 0) ? cup : cdown) + c * 8;
    const float* base = mo_sh + s * NMO_ * CSTR;

    float detA = 1.0f, detB = 1.0f;
    float minp = 1e30f;

    // ---- Phase 1: gather + factor columns 0..3 (P[j][i] = elem(row i, col j)) ----
    float P[4][8];
    {
        const int4 ci = __ldg((const int4*)cw);
        const int c4[4] = {ci.x, ci.y, ci.z, ci.w};
        #pragma unroll
        for (int j = 0; j < 4; ++j) {
            const float4 lo = *reinterpret_cast<const float4*>(base + c4[j] * CSTR);
            const float4 hi = *reinterpret_cast<const float4*>(base + c4[j] * CSTR + 4);
            P[j][0] = lo.x; P[j][1] = lo.y; P[j][2] = lo.z; P[j][3] = lo.w;
            P[j][4] = hi.x; P[j][5] = hi.y; P[j][6] = hi.z; P[j][7] = hi.w;
        }
    }
    #pragma unroll
    for (int k = 0; k < 4; ++k) {
        const float piv = P[k][k];
        minp = fminf(minp, fabsf(piv));
        if (k & 1) detB *= piv; else detA *= piv;
        const float inv = frcp_fast(piv);
        #pragma unroll
        for (int i = k + 1; i < 8; ++i) P[k][i] *= inv;        // L[i][k]
        #pragma unroll
        for (int j = k + 1; j < 4; ++j)
            #pragma unroll
            for (int i = k + 1; i < 8; ++i)
                P[j][i] = fmaf(-P[k][i], P[j][k], P[j][i]);
    }
    // Live from phase 1: only the L entries P[k][i], i > k.

    // ---- Phase 2: load trailing columns 4..7, apply panel with 4-way ILP ----
    float cv[4][8];
    {
        const int4 ci2 = __ldg((const int4*)cw + 1);
        const int c8[4] = {ci2.x, ci2.y, ci2.z, ci2.w};
        #pragma unroll
        for (int j = 0; j < 4; ++j) {
            const float4 lo = *reinterpret_cast<const float4*>(base + c8[j] * CSTR);
            const float4 hi = *reinterpret_cast<const float4*>(base + c8[j] * CSTR + 4);
            cv[j][0] = lo.x; cv[j][1] = lo.y; cv[j][2] = lo.z; cv[j][3] = lo.w;
            cv[j][4] = hi.x; cv[j][5] = hi.y; cv[j][6] = hi.z; cv[j][7] = hi.w;
        }
    }
    // Stage k eliminates row k from every column; the four columns are
    // independent, so each stage is 4 parallel FMA chains (not one long one).
    #pragma unroll
    for (int k = 0; k < 4; ++k)
        #pragma unroll
        for (int j = 0; j < 4; ++j)
            #pragma unroll
            for (int i = k + 1; i < 8; ++i)
                cv[j][i] = fmaf(-P[k][i], cv[j][k], cv[j][i]);

    // ---- Phase 3: 4x4 Schur complement LU (S[i][j] = cv[j][4+i]) ----
    #pragma unroll
    for (int k = 0; k < 4; ++k) {
        const float piv = cv[k][4 + k];
        minp = fminf(minp, fabsf(piv));
        if (k & 1) detB *= piv; else detA *= piv;
        if (k < 3) {
            const float inv = frcp_fast(piv);
            float f[4];
            #pragma unroll
            for (int i = k + 1; i < 4; ++i) f[i] = cv[k][4 + i] * inv;
            #pragma unroll
            for (int j = k + 1; j < 4; ++j)
                #pragma unroll
                for (int i = k + 1; i < 4; ++i)
                    cv[j][4 + i] = fmaf(-f[i], cv[j][4 + k], cv[j][4 + i]);
        }
    }

    float det = detA * detB;

    // ---- rare path: fp64 pivoted LU on a local array ----
    if (minp < PIV_TAU) {
        double m[64];
        #pragma unroll 1
        for (int j = 0; j < 8; ++j) {
            const int col = cw[j];
            #pragma unroll 1
            for (int i = 0; i < 8; ++i)
                m[i * 8 + j] = (double)base[col * CSTR + i];
        }
        double dd = 1.0;
        #pragma unroll 1
        for (int k = 0; k < 8; ++k) {
            int p = k;
            double mx = fabs(m[k * 8 + k]);
            for (int i = k + 1; i < 8; ++i) {
                const double v = fabs(m[i * 8 + k]);
                if (v > mx) { mx = v; p = i; }
            }
            if (p != k) {
                dd = -dd;
                for (int j2 = k; j2 < 8; ++j2) {
                    const double tmp = m[k * 8 + j2];
                    m[k * 8 + j2] = m[p * 8 + j2];
                    m[p * 8 + j2] = tmp;
                }
            }
            const double piv = m[k * 8 + k];
            dd *= piv;
            const double iv = 1.0 / piv;
            for (int i = k + 1; i < 8; ++i) {
                const double f = m[i * 8 + k] * iv;
                for (int j2 = k + 1; j2 < 8; ++j2)
                    m[i * 8 + j2] -= f * m[k * 8 + j2];
            }
        }
        det = (float)dd;
    }

    sh_det[t] = det;
    __syncthreads();

    // Combine spins; coalesced 256B store per block.
    if (t < CPB)
        out[(size_t)b * nconf + c0 + t] = sh_det[t] * sh_det[CPB + t];
}

extern "C" void kernel_launch(void* const* d_in, const int* in_sizes, int n_in,
                              void* d_out, int out_size)
{
    const float* mo    = (const float*)d_in[0];  // (B, 16, 40) f32
    const int*   cup   = (const int*)  d_in[1];  // (C, 8) i32
    const int*   cdown = (const int*)  d_in[2];  // (C, 8) i32
    float*       out   = (float*)d_out;          // (B, C) f32

    const int B = in_sizes[0] / (ROWS_ * NMO_);
    const int C = in_sizes[1] / 8;

    dim3 grid(C / CPB, B);
    slater_det_kernel<<<grid, TPB>>>(mo, cup, cdown, out, C);
}